// round 13
// baseline (speedup 1.0000x reference)
#include <cuda_runtime.h>
#include <cstdint>

// HDConvEncoder: 8-step depthwise-conv3 recurrence + LayerNorm(L) + pw scale/bias
// + GELU (A&S 7.1.28 erf, abs err 3e-7) + residual. B=32, C=256, L=4096, S=8, Cs=32.
// One block per (b,c_local) chain (1024 blocks), NT=256 threads x 16 elements each.
// 3 CTAs/SM (85-reg budget) cuts wave count 3.46 -> 2.31. Packed f32x2 math,
// X/Y state in registers, conv neighbors via 2 shuffles + 8-entry SMEM edges,
// cp.async double-buffered x staging, weights hoisted to SMEM.

#define NT 256
#define LLEN 4096
#define NG 8
#define CS 32
#define CTOT 256

typedef unsigned long long u64;

__device__ __forceinline__ uint32_t smem_u32(const void* p) {
    return (uint32_t)__cvta_generic_to_shared(p);
}
__device__ __forceinline__ u64 pk2(float lo, float hi) {
    u64 r;
    asm("mov.b64 %0, {%1, %2};" : "=l"(r) : "r"(__float_as_uint(lo)), "r"(__float_as_uint(hi)));
    return r;
}
__device__ __forceinline__ void upk2(u64 p, float& lo, float& hi) {
    uint32_t a, b;
    asm("mov.b64 {%0, %1}, %2;" : "=r"(a), "=r"(b) : "l"(p));
    lo = __uint_as_float(a); hi = __uint_as_float(b);
}
__device__ __forceinline__ u64 splat2(float v) { return pk2(v, v); }
__device__ __forceinline__ u64 fma2(u64 a, u64 b, u64 c) {
    u64 r; asm("fma.rn.f32x2 %0, %1, %2, %3;" : "=l"(r) : "l"(a), "l"(b), "l"(c)); return r;
}
__device__ __forceinline__ u64 mul2(u64 a, u64 b) {
    u64 r; asm("mul.rn.f32x2 %0, %1, %2;" : "=l"(r) : "l"(a), "l"(b)); return r;
}
__device__ __forceinline__ u64 add2(u64 a, u64 b) {
    u64 r; asm("add.rn.f32x2 %0, %1, %2;" : "=l"(r) : "l"(a), "l"(b)); return r;
}
__device__ __forceinline__ u64 abs2(u64 a) {
    u64 r; asm("and.b64 %0, %1, 0x7FFFFFFF7FFFFFFF;" : "=l"(r) : "l"(a)); return r;
}
__device__ __forceinline__ float frcp(float x) {
    float r; asm("rcp.approx.f32 %0, %1;" : "=f"(r) : "f"(x)); return r;
}

// Packed LN+pw+gelu+residual for 2 elements.
// gelu(T) = 0.5*(T + |T|*erf(|T|/sqrt2)); erf via A&S 7.1.28 (1 - w^-16),
// sqrt2 folded into coefficients; overflow-graceful (w^16->inf => rcp->0 => erf->1).
__device__ __forceinline__ u64 epilogue2(u64 Yj, u64 Xj, u64 Gj, u64 Bj,
                                         u64 RSTD, u64 C0, u64 PWW, u64 PWB) {
    const u64 ONE2 = splat2(1.0f);
    u64 T = fma2(fma2(fma2(Yj, RSTD, C0), Gj, Bj), PWW, PWB);
    u64 U = abs2(T);
    u64 w = fma2(U, splat2(5.38298e-6f),  splat2(4.88910e-5f));
    w = fma2(U, w, splat2(3.80036e-5f));
    w = fma2(U, w, splat2(0.00327768f));
    w = fma2(U, w, splat2(0.02114101f));
    w = fma2(U, w, splat2(0.04986735f));
    w = fma2(U, w, ONE2);
    u64 w2  = mul2(w,  w);
    u64 w4  = mul2(w2, w2);
    u64 w8  = mul2(w4, w4);
    u64 w16 = mul2(w8, w8);
    float r0, r1;
    upk2(w16, r0, r1);
    u64 RI  = pk2(frcp(r0), frcp(r1));
    u64 ERF = fma2(RI, splat2(-1.0f), ONE2);
    u64 R   = fma2(U, ERF, T);
    return fma2(splat2(0.5f), R, Xj);
}

__global__ void __launch_bounds__(NT, 3)
hdconv_encoder_kernel(const float* __restrict__ x,
                      const float* __restrict__ conv_w,   // [8,3,32]
                      const float* __restrict__ conv_b,   // [8,32]
                      const float* __restrict__ ln_g,     // [4096]
                      const float* __restrict__ ln_b,     // [4096]
                      const float* __restrict__ pw_w,     // [256]
                      const float* __restrict__ pw_b,     // [256]
                      float* __restrict__ out)
{
    extern __shared__ float sm[];
    float* sgam = sm;                  // 4096
    float* sbet = sm + LLEN;           // 4096
    float* xb0  = sm + 2 * LLEN;       // 4096 (x stage buf 0)
    float* xb1  = sm + 3 * LLEN;       // 4096 (x stage buf 1)
    float* eA   = sm + 4 * LLEN;       // 8: first z of each warp's 512-chunk
    float* eB   = eA + 8;              // 8: last z
    float* red  = eB + 8;              // 16: (s,ss) partials per warp
    float* swt  = red + 16;            // 48: per-block weight scalars [g*6+k]

    const int tid  = threadIdx.x;
    const int lane = tid & 31;
    const int warp = tid >> 5;         // 0..7; warp w owns elements [512w, 512w+512)
    const int b    = blockIdx.x >> 5;
    const int cl   = blockIdx.x & 31;

    const float* xbase = x   + ((long)b * CTOT + cl) * LLEN;
    float*       obase = out + ((long)b * CTOT + cl) * LLEN;

    // gamma/beta -> SMEM (own-slot access only; rides the pre-loop barrier).
#pragma unroll
    for (int k = 0; k < 4; k++) {
        ((float4*)sgam)[4 * tid + k] = ((const float4*)ln_g)[4 * tid + k];
        ((float4*)sbet)[4 * tid + k] = ((const float4*)ln_b)[4 * tid + k];
    }
    // Hoist per-block weight scalars (8 groups x 6) into SMEM once.
    if (tid < NG) {
        const int g = tid;
        swt[g * 6 + 0] = conv_w[g * 96 +  0 + cl];
        swt[g * 6 + 1] = conv_w[g * 96 + 32 + cl];
        swt[g * 6 + 2] = conv_w[g * 96 + 64 + cl];
        swt[g * 6 + 3] = conv_b[g * 32 + cl];
        swt[g * 6 + 4] = pw_w[g * 32 + cl];
        swt[g * 6 + 5] = pw_b[g * 32 + cl];
    }

    auto prefetch = [&](int i, float* buf) {
        const float* src = xbase + (long)i * CS * LLEN + 16 * tid;
        uint32_t dst = smem_u32(buf + 16 * tid);
#pragma unroll
        for (int k = 0; k < 4; k++) {
            asm volatile("cp.async.cg.shared.global [%0], [%1], 16;\n"
                         :: "r"(dst + 16u * k), "l"(src + 4 * k));
        }
        asm volatile("cp.async.commit_group;\n");
    };
    prefetch(0, xb0);

    u64 Y[8];
#pragma unroll
    for (int j = 0; j < 8; j++) Y[j] = 0ull;

    __syncthreads(); // gamma/beta + swt visible

#pragma unroll 1
    for (int i = 0; i < NG; i++) {
        float* curb = (i & 1) ? xb1 : xb0;
        float* nxtb = (i & 1) ? xb0 : xb1;
        if (i < NG - 1) {
            prefetch(i + 1, nxtb);
            asm volatile("cp.async.wait_group 1;\n");   // this iter's data ready
        } else {
            asm volatile("cp.async.wait_group 0;\n");
        }

        // x from own SMEM slots -> registers; z = x + y_prev (packed).
        u64 X[8];
#pragma unroll
        for (int k = 0; k < 4; k++) {
            float4 xv = ((const float4*)curb)[4 * tid + k];
            X[2 * k]     = pk2(xv.x, xv.y);
            X[2 * k + 1] = pk2(xv.z, xv.w);
        }
#pragma unroll
        for (int j = 0; j < 8; j++) Y[j] = add2(Y[j], X[j]);

        const float w0 = swt[i * 6 + 0];
        const float w1 = swt[i * 6 + 1];
        const float w2 = swt[i * 6 + 2];
        const float bb = swt[i * 6 + 3];

        float z[16];
#pragma unroll
        for (int j = 0; j < 8; j++) upk2(Y[j], z[2 * j], z[2 * j + 1]);

        // Publish warp-chunk edges; one barrier makes them visible.
        if (lane == 0)  eA[warp] = z[0];
        if (lane == 31) eB[warp] = z[15];
        __syncthreads();

        // Cross-thread taps (contiguous 16-elem segments -> only 2 shuffles).
        float zmw = __shfl_up_sync(0xFFFFFFFFu, z[15], 1);
        float zpx = __shfl_down_sync(0xFFFFFFFFu, z[0], 1);
        float zm = (lane == 0)  ? ((warp == 0) ? 0.f : eB[warp - 1]) : zmw;
        float zp = (lane == 31) ? ((warp == 7) ? 0.f : eA[warp + 1]) : zpx;

        // conv3 packed. Shifted pairs M[j] = (z[2j-1], z[2j]), j=0..8 (L_{j+1}==R_j).
        {
            const u64 W0 = splat2(w0), W1 = splat2(w1), W2 = splat2(w2), BB = splat2(bb);
            u64 M[9];
            M[0] = pk2(zm, z[0]);
#pragma unroll
            for (int j = 1; j < 8; j++) M[j] = pk2(z[2 * j - 1], z[2 * j]);
            M[8] = pk2(z[15], zp);
#pragma unroll
            for (int j = 0; j < 8; j++)
                Y[j] = fma2(W0, M[j], fma2(W1, Y[j], fma2(W2, M[j + 1], BB)));
        }

        // Packed partial sums -> warp reduce -> 8 SMEM partial pairs.
        float s, ss;
        {
            u64 PS  = add2(add2(add2(Y[0], Y[1]), add2(Y[2], Y[3])),
                           add2(add2(Y[4], Y[5]), add2(Y[6], Y[7])));
            u64 PSS = mul2(Y[0], Y[0]);
#pragma unroll
            for (int j = 1; j < 8; j++) PSS = fma2(Y[j], Y[j], PSS);
            float s0, s1, q0, q1;
            upk2(PS, s0, s1); upk2(PSS, q0, q1);
            s = s0 + s1; ss = q0 + q1;
        }
#pragma unroll
        for (int o = 16; o > 0; o >>= 1) {
            s  += __shfl_xor_sync(0xFFFFFFFFu, s,  o);
            ss += __shfl_xor_sync(0xFFFFFFFFu, ss, o);
        }
        if (lane == 0) { red[2 * warp] = s; red[2 * warp + 1] = ss; }
        __syncthreads();
        // Every warp redundantly reduces the 8 partials (no broadcast barrier).
        float a = (lane < 8) ? red[2 * lane]     : 0.f;
        float c = (lane < 8) ? red[2 * lane + 1] : 0.f;
#pragma unroll
        for (int o = 4; o > 0; o >>= 1) {
            a += __shfl_xor_sync(0xFFFFFFFFu, a, o);
            c += __shfl_xor_sync(0xFFFFFFFFu, c, o);
        }
        a = __shfl_sync(0xFFFFFFFFu, a, 0);
        c = __shfl_sync(0xFFFFFFFFu, c, 0);

        const float mean = a * (1.0f / (float)LLEN);
        const float rstd = rsqrtf(c * (1.0f / (float)LLEN) - mean * mean + 1e-6f);
        const u64 RSTD = splat2(rstd);
        const u64 C0   = splat2(-mean * rstd);
        const u64 PWW  = splat2(swt[i * 6 + 4]);
        const u64 PWB  = splat2(swt[i * 6 + 5]);

        // Epilogue per float4 quarter; streaming stores.
        float* orow = obase + (long)i * CS * LLEN;
#pragma unroll
        for (int k = 0; k < 4; k++) {
            float4 g  = ((const float4*)sgam)[4 * tid + k];
            float4 be = ((const float4*)sbet)[4 * tid + k];
            u64 Olo = epilogue2(Y[2 * k],     X[2 * k],     pk2(g.x, g.y), pk2(be.x, be.y),
                                RSTD, C0, PWW, PWB);
            u64 Ohi = epilogue2(Y[2 * k + 1], X[2 * k + 1], pk2(g.z, g.w), pk2(be.z, be.w),
                                RSTD, C0, PWW, PWB);
            float4 o;
            upk2(Olo, o.x, o.y); upk2(Ohi, o.z, o.w);
            __stcs(((float4*)orow) + 4 * tid + k, o);
        }
    }
}

extern "C" void kernel_launch(void* const* d_in, const int* in_sizes, int n_in,
                              void* d_out, int out_size)
{
    const float* x      = (const float*)d_in[0];
    const float* conv_w = (const float*)d_in[1];
    const float* conv_b = (const float*)d_in[2];
    const float* ln_g   = (const float*)d_in[3];
    const float* ln_b   = (const float*)d_in[4];
    const float* pw_w   = (const float*)d_in[5];
    const float* pw_b   = (const float*)d_in[6];
    float* out = (float*)d_out;

    const int smem_bytes = (4 * LLEN + 80) * (int)sizeof(float); // 65856
    cudaFuncSetAttribute(hdconv_encoder_kernel,
                         cudaFuncAttributeMaxDynamicSharedMemorySize, smem_bytes);

    dim3 grid(32 * 32); // B * Cs = 1024 chains
    dim3 block(NT);
    hdconv_encoder_kernel<<<grid, block, smem_bytes>>>(
        x, conv_w, conv_b, ln_g, ln_b, pw_w, pw_b, out);
}

// round 15
// speedup vs baseline: 1.3844x; 1.3844x over previous
#include <cuda_runtime.h>
#include <cstdint>

// HDConvEncoder: 8-step depthwise-conv3 recurrence + LayerNorm(L) + pw scale/bias
// + GELU (A&S 7.1.28 erf, abs err 3e-7) + residual. B=32, C=256, L=4096, S=8, Cs=32.
// One block per (b,c_local) chain (1024 blocks), NT=512, 8 elem/thread, occ 2.
// R11 winner + stage-2 reduction rewritten as broadcast LDS.128 of the packed
// (s,ss) pairs + f32x2 add tree: 23 instrs / ~60 serial cycles instead of
// 10 dependent SHFLs / ~260 cycles at the all-warps-lockstep point.
// (redux.sync.add.f32 is NOT available on sm_103 — R13 build failure.)

#define NT 512
#define LLEN 4096
#define NG 8
#define CS 32
#define CTOT 256

typedef unsigned long long u64;

__device__ __forceinline__ uint32_t smem_u32(const void* p) {
    return (uint32_t)__cvta_generic_to_shared(p);
}
__device__ __forceinline__ u64 pk2(float lo, float hi) {
    u64 r;
    asm("mov.b64 %0, {%1, %2};" : "=l"(r) : "r"(__float_as_uint(lo)), "r"(__float_as_uint(hi)));
    return r;
}
__device__ __forceinline__ void upk2(u64 p, float& lo, float& hi) {
    uint32_t a, b;
    asm("mov.b64 {%0, %1}, %2;" : "=r"(a), "=r"(b) : "l"(p));
    lo = __uint_as_float(a); hi = __uint_as_float(b);
}
__device__ __forceinline__ u64 splat2(float v) { return pk2(v, v); }
__device__ __forceinline__ u64 fma2(u64 a, u64 b, u64 c) {
    u64 r; asm("fma.rn.f32x2 %0, %1, %2, %3;" : "=l"(r) : "l"(a), "l"(b), "l"(c)); return r;
}
__device__ __forceinline__ u64 mul2(u64 a, u64 b) {
    u64 r; asm("mul.rn.f32x2 %0, %1, %2;" : "=l"(r) : "l"(a), "l"(b)); return r;
}
__device__ __forceinline__ u64 add2(u64 a, u64 b) {
    u64 r; asm("add.rn.f32x2 %0, %1, %2;" : "=l"(r) : "l"(a), "l"(b)); return r;
}
__device__ __forceinline__ u64 abs2(u64 a) {
    u64 r; asm("and.b64 %0, %1, 0x7FFFFFFF7FFFFFFF;" : "=l"(r) : "l"(a)); return r;
}
__device__ __forceinline__ float frcp(float x) {
    float r; asm("rcp.approx.f32 %0, %1;" : "=f"(r) : "f"(x)); return r;
}

// Packed LN+pw+gelu+residual for 2 elements.
// gelu(T) = 0.5*(T + |T|*erf(|T|/sqrt2)); erf via A&S 7.1.28 (1 - w^-16),
// sqrt2 folded into coefficients; overflow-graceful (w^16->inf => rcp->0 => erf->1).
__device__ __forceinline__ u64 epilogue2(u64 Yj, u64 Xj, u64 Gj, u64 Bj,
                                         u64 RSTD, u64 C0, u64 PWW, u64 PWB) {
    const u64 ONE2 = splat2(1.0f);
    u64 T = fma2(fma2(fma2(Yj, RSTD, C0), Gj, Bj), PWW, PWB);
    u64 U = abs2(T);
    u64 w = fma2(U, splat2(5.38298e-6f),  splat2(4.88910e-5f));
    w = fma2(U, w, splat2(3.80036e-5f));
    w = fma2(U, w, splat2(0.00327768f));
    w = fma2(U, w, splat2(0.02114101f));
    w = fma2(U, w, splat2(0.04986735f));
    w = fma2(U, w, ONE2);
    u64 w2  = mul2(w,  w);
    u64 w4  = mul2(w2, w2);
    u64 w8  = mul2(w4, w4);
    u64 w16 = mul2(w8, w8);
    float r0, r1;
    upk2(w16, r0, r1);
    u64 RI  = pk2(frcp(r0), frcp(r1));       // w^-16
    u64 ERF = fma2(RI, splat2(-1.0f), ONE2); // 1 - w^-16
    u64 R   = fma2(U, ERF, T);               // T + |T|*erf
    return fma2(splat2(0.5f), R, Xj);        // x + 0.5*(...)
}

__global__ void __launch_bounds__(NT, 2)
hdconv_encoder_kernel(const float* __restrict__ x,
                      const float* __restrict__ conv_w,   // [8,3,32]
                      const float* __restrict__ conv_b,   // [8,32]
                      const float* __restrict__ ln_g,     // [4096]
                      const float* __restrict__ ln_b,     // [4096]
                      const float* __restrict__ pw_w,     // [256]
                      const float* __restrict__ pw_b,     // [256]
                      float* __restrict__ out)
{
    extern __shared__ float sm[];
    float* sgam = sm;                  // 4096
    float* sbet = sm + LLEN;           // 4096
    float* xb0  = sm + 2 * LLEN;       // 4096 (x stage buf 0)
    float* xb1  = sm + 3 * LLEN;       // 4096 (x stage buf 1)
    float* eA   = sm + 4 * LLEN;       // 32 first-z per warp-chunk
    float* eB   = eA + 32;             // 32 last-z per warp-chunk
    float* red  = eB + 32;             // 32 floats: 16 packed (s,ss) pairs, 16B-aligned
    float* swt  = red + 32;            // 48 per-block weight scalars [g*6 + k]

    const int tid  = threadIdx.x;
    const int lane = tid & 31;
    const int warp = tid >> 5;
    const int b    = blockIdx.x >> 5;
    const int cl   = blockIdx.x & 31;

    const float* xbase = x   + ((long)b * CTOT + cl) * LLEN;
    float*       obase = out + ((long)b * CTOT + cl) * LLEN;

    // gamma/beta -> SMEM (own-slot access only; rides the pre-loop barrier).
    ((float4*)sgam)[tid]      = ((const float4*)ln_g)[tid];
    ((float4*)sgam)[tid + NT] = ((const float4*)ln_g)[tid + NT];
    ((float4*)sbet)[tid]      = ((const float4*)ln_b)[tid];
    ((float4*)sbet)[tid + NT] = ((const float4*)ln_b)[tid + NT];

    // Hoist ALL per-block weight scalars (8 groups x 6) into SMEM once.
    if (tid < NG) {
        const int g = tid;
        swt[g * 6 + 0] = conv_w[g * 96 +  0 + cl];
        swt[g * 6 + 1] = conv_w[g * 96 + 32 + cl];
        swt[g * 6 + 2] = conv_w[g * 96 + 64 + cl];
        swt[g * 6 + 3] = conv_b[g * 32 + cl];
        swt[g * 6 + 4] = pw_w[g * 32 + cl];
        swt[g * 6 + 5] = pw_b[g * 32 + cl];
    }

    auto prefetch = [&](int i, float* buf) {
        const float* src = xbase + (long)i * CS * LLEN;
        uint32_t d0 = smem_u32(buf + 4 * tid);
        uint32_t d1 = smem_u32(buf + 4 * (tid + NT));
        asm volatile("cp.async.cg.shared.global [%0], [%1], 16;\n" :: "r"(d0), "l"(src + 4 * tid));
        asm volatile("cp.async.cg.shared.global [%0], [%1], 16;\n" :: "r"(d1), "l"(src + 4 * (tid + NT)));
        asm volatile("cp.async.commit_group;\n");
    };
    prefetch(0, xb0);

    u64 Y0 = 0ull, Y1 = 0ull, Y2 = 0ull, Y3 = 0ull;

    const int wq0 = tid >> 5;          // warp-chunk id of first half (0..15)
    const int wq1 = wq0 + 16;          // warp-chunk id of second half (16..31)

    __syncthreads(); // gamma/beta + swt visible

#pragma unroll 1
    for (int i = 0; i < NG; i++) {
        float* curb = (i & 1) ? xb1 : xb0;
        float* nxtb = (i & 1) ? xb0 : xb1;
        if (i < NG - 1) {
            prefetch(i + 1, nxtb);
            asm volatile("cp.async.wait_group 1;\n");   // wait for THIS iter's data
        } else {
            asm volatile("cp.async.wait_group 0;\n");
        }

        // x for this group from own SMEM slots.
        u64 X0, X1, X2, X3;
        {
            float4 xa = ((const float4*)curb)[tid];
            X0 = pk2(xa.x, xa.y); X1 = pk2(xa.z, xa.w);
            float4 xb = ((const float4*)curb)[tid + NT];
            X2 = pk2(xb.x, xb.y); X3 = pk2(xb.z, xb.w);
        }
        // z = x + y_prev
        Y0 = add2(Y0, X0); Y1 = add2(Y1, X1);
        Y2 = add2(Y2, X2); Y3 = add2(Y3, X3);

        // Per-group scalars: broadcast LDS (hoisted at block start).
        const float w0 = swt[i * 6 + 0];
        const float w1 = swt[i * 6 + 1];
        const float w2 = swt[i * 6 + 2];
        const float bb = swt[i * 6 + 3];

        float z0, z1, z2, z3, z4_, z5, z6, z7;
        upk2(Y0, z0, z1); upk2(Y1, z2, z3);
        upk2(Y2, z4_, z5); upk2(Y3, z6, z7);

        if (lane == 0)  { eA[wq0] = z0; eA[wq1] = z4_; }
        if (lane == 31) { eB[wq0] = z3; eB[wq1] = z7; }
        __syncthreads();

        float zmw0 = __shfl_up_sync(0xFFFFFFFFu, z3, 1);
        float zpx0 = __shfl_down_sync(0xFFFFFFFFu, z0, 1);
        float zmw1 = __shfl_up_sync(0xFFFFFFFFu, z7, 1);
        float zpx1 = __shfl_down_sync(0xFFFFFFFFu, z4_, 1);
        // First half spans chunks 0..15: left edge of chunk 0 is zero pad,
        // lane-31 right neighbor always exists (chunk wq0+1 <= 16).
        float zm0 = (lane == 0)  ? ((wq0 == 0) ? 0.f : eB[wq0 - 1]) : zmw0;
        float zp0 = (lane == 31) ? eA[wq0 + 1] : zpx0;
        // Second half spans chunks 16..31: left neighbor always exists,
        // right edge of chunk 31 is zero pad.
        float zm1 = (lane == 0)  ? eB[wq1 - 1] : zmw1;
        float zp1 = (lane == 31) ? ((wq1 == 31) ? 0.f : eA[wq1 + 1]) : zpx1;

        // conv3 packed: Y = w0*zm + w1*zc + w2*zp + bb
        {
            const u64 W0 = splat2(w0), W1 = splat2(w1), W2 = splat2(w2), BB = splat2(bb);
            u64 t;
            u64 C01 = pk2(z1, z2);
            t = fma2(W2, C01, BB); t = fma2(W1, Y0, t); u64 n0 = fma2(W0, pk2(zm0, z0), t);
            t = fma2(W2, pk2(z3, zp0), BB); t = fma2(W1, Y1, t); Y1 = fma2(W0, C01, t);
            Y0 = n0;
            u64 C23 = pk2(z5, z6);
            t = fma2(W2, C23, BB); t = fma2(W1, Y2, t); u64 n2 = fma2(W0, pk2(zm1, z4_), t);
            t = fma2(W2, pk2(z7, zp1), BB); t = fma2(W1, Y3, t); Y3 = fma2(W0, C23, t);
            Y2 = n2;
        }

        // Stage 1: packed partial sums -> shfl-xor warp reduce -> packed SMEM pair.
        float s, ss;
        {
            u64 PS  = add2(add2(Y0, Y1), add2(Y2, Y3));
            u64 PSS = fma2(Y0, Y0, fma2(Y1, Y1, fma2(Y2, Y2, mul2(Y3, Y3))));
            float s0, s1, q0, q1;
            upk2(PS, s0, s1); upk2(PSS, q0, q1);
            s = s0 + s1; ss = q0 + q1;
        }
#pragma unroll
        for (int o = 16; o > 0; o >>= 1) {
            s  += __shfl_xor_sync(0xFFFFFFFFu, s,  o);
            ss += __shfl_xor_sync(0xFFFFFFFFu, ss, o);
        }
        if (lane == 0) { red[2 * warp] = s; red[2 * warp + 1] = ss; }
        __syncthreads();

        // Stage 2: every thread sums the 16 packed (s,ss) pairs via broadcast
        // LDS.128 + f32x2 add tree (short serial chain, no shuffles).
        float a, c;
        {
            const float4* r4 = (const float4*)red;
            float4 p0 = r4[0], p1 = r4[1], p2 = r4[2], p3 = r4[3];
            float4 p4 = r4[4], p5 = r4[5], p6 = r4[6], p7 = r4[7];
            u64 t0 = add2(pk2(p0.x, p0.y), pk2(p0.z, p0.w));
            u64 t1 = add2(pk2(p1.x, p1.y), pk2(p1.z, p1.w));
            u64 t2 = add2(pk2(p2.x, p2.y), pk2(p2.z, p2.w));
            u64 t3 = add2(pk2(p3.x, p3.y), pk2(p3.z, p3.w));
            u64 t4 = add2(pk2(p4.x, p4.y), pk2(p4.z, p4.w));
            u64 t5 = add2(pk2(p5.x, p5.y), pk2(p5.z, p5.w));
            u64 t6 = add2(pk2(p6.x, p6.y), pk2(p6.z, p6.w));
            u64 t7 = add2(pk2(p7.x, p7.y), pk2(p7.z, p7.w));
            u64 u0 = add2(add2(t0, t1), add2(t2, t3));
            u64 u1 = add2(add2(t4, t5), add2(t6, t7));
            u64 T  = add2(u0, u1);
            upk2(T, a, c);
        }

        const float mean = a * (1.0f / (float)LLEN);
        const float rstd = rsqrtf(c * (1.0f / (float)LLEN) - mean * mean + 1e-6f);
        const u64 RSTD = splat2(rstd);
        const u64 C0   = splat2(-mean * rstd);
        const u64 PWW  = splat2(swt[i * 6 + 4]);
        const u64 PWB  = splat2(swt[i * 6 + 5]);

        // Epilogue (X from registers, gamma/beta from SMEM own slots).
        float* orow = obase + (long)i * CS * LLEN;
        {
            float4 g  = ((const float4*)sgam)[tid];
            float4 be = ((const float4*)sbet)[tid];
            u64 O0 = epilogue2(Y0, X0, pk2(g.x, g.y), pk2(be.x, be.y), RSTD, C0, PWW, PWB);
            u64 O1 = epilogue2(Y1, X1, pk2(g.z, g.w), pk2(be.z, be.w), RSTD, C0, PWW, PWB);
            float4 o;
            upk2(O0, o.x, o.y); upk2(O1, o.z, o.w);
            __stcs(((float4*)orow) + tid, o);
        }
        {
            float4 g  = ((const float4*)sgam)[tid + NT];
            float4 be = ((const float4*)sbet)[tid + NT];
            u64 O2 = epilogue2(Y2, X2, pk2(g.x, g.y), pk2(be.x, be.y), RSTD, C0, PWW, PWB);
            u64 O3 = epilogue2(Y3, X3, pk2(g.z, g.w), pk2(be.z, be.w), RSTD, C0, PWW, PWB);
            float4 o;
            upk2(O2, o.x, o.y); upk2(O3, o.z, o.w);
            __stcs(((float4*)orow) + tid + NT, o);
        }
    }
}

extern "C" void kernel_launch(void* const* d_in, const int* in_sizes, int n_in,
                              void* d_out, int out_size)
{
    const float* x      = (const float*)d_in[0];
    const float* conv_w = (const float*)d_in[1];
    const float* conv_b = (const float*)d_in[2];
    const float* ln_g   = (const float*)d_in[3];
    const float* ln_b   = (const float*)d_in[4];
    const float* pw_w   = (const float*)d_in[5];
    const float* pw_b   = (const float*)d_in[6];
    float* out = (float*)d_out;

    const int smem_bytes = (4 * LLEN + 160) * (int)sizeof(float); // 66176
    cudaFuncSetAttribute(hdconv_encoder_kernel,
                         cudaFuncAttributeMaxDynamicSharedMemorySize, smem_bytes);

    dim3 grid(32 * 32);
    dim3 block(NT);
    hdconv_encoder_kernel<<<grid, block, smem_bytes>>>(
        x, conv_w, conv_b, ln_g, ln_b, pw_w, pw_b, out);
}

// round 17
// speedup vs baseline: 1.4595x; 1.0543x over previous
#include <cuda_runtime.h>
#include <cstdint>

// HDConvEncoder: 8-step depthwise-conv3 recurrence + LayerNorm(L) + pw scale/bias
// + GELU (A&S 7.1.28 erf, abs err 3e-7) + residual. B=32, C=256, L=4096, S=8, Cs=32.
// PERSISTENT version of the R11 winner: grid = 296 blocks (2/SM), each block
// loops over chains (chain += 296). Gamma/beta SMEM fill paid once per block
// (was ~7x per SM); next chain's group-0 x prefetched during current chain's
// last iteration (no cold-start DRAM exposure at chain seams); swt double-
// buffered by chain parity and covered by the i=0 edge barrier.

#define NT 512
#define LLEN 4096
#define NG 8
#define CS 32
#define CTOT 256
#define NCHAIN 1024
#define GRIDN 296

typedef unsigned long long u64;

__device__ __forceinline__ uint32_t smem_u32(const void* p) {
    return (uint32_t)__cvta_generic_to_shared(p);
}
__device__ __forceinline__ u64 pk2(float lo, float hi) {
    u64 r;
    asm("mov.b64 %0, {%1, %2};" : "=l"(r) : "r"(__float_as_uint(lo)), "r"(__float_as_uint(hi)));
    return r;
}
__device__ __forceinline__ void upk2(u64 p, float& lo, float& hi) {
    uint32_t a, b;
    asm("mov.b64 {%0, %1}, %2;" : "=r"(a), "=r"(b) : "l"(p));
    lo = __uint_as_float(a); hi = __uint_as_float(b);
}
__device__ __forceinline__ u64 splat2(float v) { return pk2(v, v); }
__device__ __forceinline__ u64 fma2(u64 a, u64 b, u64 c) {
    u64 r; asm("fma.rn.f32x2 %0, %1, %2, %3;" : "=l"(r) : "l"(a), "l"(b), "l"(c)); return r;
}
__device__ __forceinline__ u64 mul2(u64 a, u64 b) {
    u64 r; asm("mul.rn.f32x2 %0, %1, %2;" : "=l"(r) : "l"(a), "l"(b)); return r;
}
__device__ __forceinline__ u64 add2(u64 a, u64 b) {
    u64 r; asm("add.rn.f32x2 %0, %1, %2;" : "=l"(r) : "l"(a), "l"(b)); return r;
}
__device__ __forceinline__ u64 abs2(u64 a) {
    u64 r; asm("and.b64 %0, %1, 0x7FFFFFFF7FFFFFFF;" : "=l"(r) : "l"(a)); return r;
}
__device__ __forceinline__ float frcp(float x) {
    float r; asm("rcp.approx.f32 %0, %1;" : "=f"(r) : "f"(x)); return r;
}

// Packed LN+pw+gelu+residual for 2 elements.
// gelu(T) = 0.5*(T + |T|*erf(|T|/sqrt2)); erf via A&S 7.1.28 (1 - w^-16),
// sqrt2 folded into coefficients; overflow-graceful (w^16->inf => rcp->0 => erf->1).
__device__ __forceinline__ u64 epilogue2(u64 Yj, u64 Xj, u64 Gj, u64 Bj,
                                         u64 RSTD, u64 C0, u64 PWW, u64 PWB) {
    const u64 ONE2 = splat2(1.0f);
    u64 T = fma2(fma2(fma2(Yj, RSTD, C0), Gj, Bj), PWW, PWB);
    u64 U = abs2(T);
    u64 w = fma2(U, splat2(5.38298e-6f),  splat2(4.88910e-5f));
    w = fma2(U, w, splat2(3.80036e-5f));
    w = fma2(U, w, splat2(0.00327768f));
    w = fma2(U, w, splat2(0.02114101f));
    w = fma2(U, w, splat2(0.04986735f));
    w = fma2(U, w, ONE2);
    u64 w2  = mul2(w,  w);
    u64 w4  = mul2(w2, w2);
    u64 w8  = mul2(w4, w4);
    u64 w16 = mul2(w8, w8);
    float r0, r1;
    upk2(w16, r0, r1);
    u64 RI  = pk2(frcp(r0), frcp(r1));       // w^-16
    u64 ERF = fma2(RI, splat2(-1.0f), ONE2); // 1 - w^-16
    u64 R   = fma2(U, ERF, T);               // T + |T|*erf
    return fma2(splat2(0.5f), R, Xj);        // x + 0.5*(...)
}

__global__ void __launch_bounds__(NT, 2)
hdconv_encoder_kernel(const float* __restrict__ x,
                      const float* __restrict__ conv_w,   // [8,3,32]
                      const float* __restrict__ conv_b,   // [8,32]
                      const float* __restrict__ ln_g,     // [4096]
                      const float* __restrict__ ln_b,     // [4096]
                      const float* __restrict__ pw_w,     // [256]
                      const float* __restrict__ pw_b,     // [256]
                      float* __restrict__ out)
{
    extern __shared__ float sm[];
    float* sgam = sm;                  // 4096
    float* sbet = sm + LLEN;           // 4096
    float* xb0  = sm + 2 * LLEN;       // 4096 (x stage buf 0)
    float* xb1  = sm + 3 * LLEN;       // 4096 (x stage buf 1)
    float* eA   = sm + 4 * LLEN;       // 32 first-z per warp-chunk
    float* eB   = eA + 32;             // 32 last-z per warp-chunk
    float* red  = eB + 32;             // 32 (s,ss) partials
    float* swt  = red + 32;            // 2x48 per-chain weight scalars (chain parity)

    const int tid  = threadIdx.x;
    const int lane = tid & 31;
    const int warp = tid >> 5;

    // gamma/beta -> SMEM ONCE per persistent block (own-slot access only).
    ((float4*)sgam)[tid]      = ((const float4*)ln_g)[tid];
    ((float4*)sgam)[tid + NT] = ((const float4*)ln_g)[tid + NT];
    ((float4*)sbet)[tid]      = ((const float4*)ln_b)[tid];
    ((float4*)sbet)[tid + NT] = ((const float4*)ln_b)[tid + NT];

    auto prefetch = [&](const float* xb_, int i, float* buf) {
        const float* src = xb_ + (long)i * CS * LLEN;
        uint32_t d0 = smem_u32(buf + 4 * tid);
        uint32_t d1 = smem_u32(buf + 4 * (tid + NT));
        asm volatile("cp.async.cg.shared.global [%0], [%1], 16;\n" :: "r"(d0), "l"(src + 4 * tid));
        asm volatile("cp.async.cg.shared.global [%0], [%1], 16;\n" :: "r"(d1), "l"(src + 4 * (tid + NT)));
        asm volatile("cp.async.commit_group;\n");
    };

    auto load_swt = [&](int chain_, int cpar_) {
        if (tid < NG) {
            const int g  = tid;
            const int cl_ = chain_ & 31;
            float* sw = swt + cpar_ * 48;
            sw[g * 6 + 0] = conv_w[g * 96 +  0 + cl_];
            sw[g * 6 + 1] = conv_w[g * 96 + 32 + cl_];
            sw[g * 6 + 2] = conv_w[g * 96 + 64 + cl_];
            sw[g * 6 + 3] = conv_b[g * 32 + cl_];
            sw[g * 6 + 4] = pw_w[g * 32 + cl_];
            sw[g * 6 + 5] = pw_b[g * 32 + cl_];
        }
    };

    const int wq0 = tid >> 5;          // warp-chunk id of first half (0..15)
    const int wq1 = wq0 + 16;          // warp-chunk id of second half (16..31)

    int chain = blockIdx.x;            // 0..295, step +296
    int cpar  = 0;
    const float* xbase = x   + (long)chain * LLEN; // (b*CTOT+cl)*LLEN == chain-major: b=chain>>5, cl=chain&31 -> ((b<<5)+cl)*LLEN = chain*LLEN? NO.
    // chain = b*32 + cl maps to row (b*CTOT + cl) = b*256 + cl. Compute explicitly:
    xbase = x + ((long)(chain >> 5) * CTOT + (chain & 31)) * LLEN;
    float* obase = out + ((long)(chain >> 5) * CTOT + (chain & 31)) * LLEN;

    load_swt(chain, cpar);             // covered by i=0's edge barrier
    prefetch(xbase, 0, xb0);

    u64 Y0 = 0ull, Y1 = 0ull, Y2 = 0ull, Y3 = 0ull;

    while (true) {
#pragma unroll 1
        for (int i = 0; i < NG; i++) {
            float* curb = (i & 1) ? xb1 : xb0;
            float* nxtb = (i & 1) ? xb0 : xb1;
            if (i < NG - 1) {
                prefetch(xbase, i + 1, nxtb);
                asm volatile("cp.async.wait_group 1;\n");   // this iter's data ready
            } else if (chain + GRIDN < NCHAIN) {
                // Prefetch NEXT chain's group 0 into nxtb (= next chain's i=0 curb).
                const int nc = chain + GRIDN;
                const float* nxb = x + ((long)(nc >> 5) * CTOT + (nc & 31)) * LLEN;
                prefetch(nxb, 0, nxtb);
                asm volatile("cp.async.wait_group 1;\n");
            } else {
                asm volatile("cp.async.wait_group 0;\n");
            }

            // x for this group from own SMEM slots.
            u64 X0, X1, X2, X3;
            {
                float4 xa = ((const float4*)curb)[tid];
                X0 = pk2(xa.x, xa.y); X1 = pk2(xa.z, xa.w);
                float4 xb = ((const float4*)curb)[tid + NT];
                X2 = pk2(xb.x, xb.y); X3 = pk2(xb.z, xb.w);
            }
            // z = x + y_prev
            Y0 = add2(Y0, X0); Y1 = add2(Y1, X1);
            Y2 = add2(Y2, X2); Y3 = add2(Y3, X3);

            float z0, z1, z2, z3, z4_, z5, z6, z7;
            upk2(Y0, z0, z1); upk2(Y1, z2, z3);
            upk2(Y2, z4_, z5); upk2(Y3, z6, z7);

            if (lane == 0)  { eA[wq0] = z0; eA[wq1] = z4_; }
            if (lane == 31) { eB[wq0] = z3; eB[wq1] = z7; }
            __syncthreads();   // edges visible; also covers this chain's swt writes (i=0)

            // Per-group scalars: broadcast LDS (after barrier -> swt writes covered).
            const float* sw = swt + cpar * 48;
            const float w0 = sw[i * 6 + 0];
            const float w1 = sw[i * 6 + 1];
            const float w2 = sw[i * 6 + 2];
            const float bb = sw[i * 6 + 3];

            float zmw0 = __shfl_up_sync(0xFFFFFFFFu, z3, 1);
            float zpx0 = __shfl_down_sync(0xFFFFFFFFu, z0, 1);
            float zmw1 = __shfl_up_sync(0xFFFFFFFFu, z7, 1);
            float zpx1 = __shfl_down_sync(0xFFFFFFFFu, z4_, 1);
            // First half spans chunks 0..15: left edge of chunk 0 is zero pad,
            // lane-31 right neighbor always exists (chunk wq0+1 <= 16).
            float zm0 = (lane == 0)  ? ((wq0 == 0) ? 0.f : eB[wq0 - 1]) : zmw0;
            float zp0 = (lane == 31) ? eA[wq0 + 1] : zpx0;
            // Second half spans chunks 16..31: left neighbor always exists,
            // right edge of chunk 31 is zero pad.
            float zm1 = (lane == 0)  ? eB[wq1 - 1] : zmw1;
            float zp1 = (lane == 31) ? ((wq1 == 31) ? 0.f : eA[wq1 + 1]) : zpx1;

            // conv3 packed: Y = w0*zm + w1*zc + w2*zp + bb
            {
                const u64 W0 = splat2(w0), W1 = splat2(w1), W2 = splat2(w2), BB = splat2(bb);
                u64 t;
                u64 C01 = pk2(z1, z2);
                t = fma2(W2, C01, BB); t = fma2(W1, Y0, t); u64 n0 = fma2(W0, pk2(zm0, z0), t);
                t = fma2(W2, pk2(z3, zp0), BB); t = fma2(W1, Y1, t); Y1 = fma2(W0, C01, t);
                Y0 = n0;
                u64 C23 = pk2(z5, z6);
                t = fma2(W2, C23, BB); t = fma2(W1, Y2, t); u64 n2 = fma2(W0, pk2(zm1, z4_), t);
                t = fma2(W2, pk2(z7, zp1), BB); t = fma2(W1, Y3, t); Y3 = fma2(W0, C23, t);
                Y2 = n2;
            }

            // Stage 1: packed partial sums -> shfl-xor warp reduce -> SMEM partials.
            float s, ss;
            {
                u64 PS  = add2(add2(Y0, Y1), add2(Y2, Y3));
                u64 PSS = fma2(Y0, Y0, fma2(Y1, Y1, fma2(Y2, Y2, mul2(Y3, Y3))));
                float s0, s1, q0, q1;
                upk2(PS, s0, s1); upk2(PSS, q0, q1);
                s = s0 + s1; ss = q0 + q1;
            }
#pragma unroll
            for (int o = 16; o > 0; o >>= 1) {
                s  += __shfl_xor_sync(0xFFFFFFFFu, s,  o);
                ss += __shfl_xor_sync(0xFFFFFFFFu, ss, o);
            }
            if (lane == 0) { red[2 * warp] = s; red[2 * warp + 1] = ss; }
            __syncthreads();
            // Stage 2: every warp redundantly reduces the 16 partials.
            float a = (lane < 16) ? red[2 * lane]     : 0.f;
            float c = (lane < 16) ? red[2 * lane + 1] : 0.f;
#pragma unroll
            for (int o = 8; o > 0; o >>= 1) {
                a += __shfl_xor_sync(0xFFFFFFFFu, a, o);
                c += __shfl_xor_sync(0xFFFFFFFFu, c, o);
            }
            a = __shfl_sync(0xFFFFFFFFu, a, 0);
            c = __shfl_sync(0xFFFFFFFFu, c, 0);

            const float mean = a * (1.0f / (float)LLEN);
            const float rstd = rsqrtf(c * (1.0f / (float)LLEN) - mean * mean + 1e-6f);
            const u64 RSTD = splat2(rstd);
            const u64 C0   = splat2(-mean * rstd);
            const u64 PWW  = splat2(sw[i * 6 + 4]);
            const u64 PWB  = splat2(sw[i * 6 + 5]);

            // Epilogue (X from registers, gamma/beta from SMEM own slots).
            float* orow = obase + (long)i * CS * LLEN;
            {
                float4 g  = ((const float4*)sgam)[tid];
                float4 be = ((const float4*)sbet)[tid];
                u64 O0 = epilogue2(Y0, X0, pk2(g.x, g.y), pk2(be.x, be.y), RSTD, C0, PWW, PWB);
                u64 O1 = epilogue2(Y1, X1, pk2(g.z, g.w), pk2(be.z, be.w), RSTD, C0, PWW, PWB);
                float4 o;
                upk2(O0, o.x, o.y); upk2(O1, o.z, o.w);
                __stcs(((float4*)orow) + tid, o);
            }
            {
                float4 g  = ((const float4*)sgam)[tid + NT];
                float4 be = ((const float4*)sbet)[tid + NT];
                u64 O2 = epilogue2(Y2, X2, pk2(g.x, g.y), pk2(be.x, be.y), RSTD, C0, PWW, PWB);
                u64 O3 = epilogue2(Y3, X3, pk2(g.z, g.w), pk2(be.z, be.w), RSTD, C0, PWW, PWB);
                float4 o;
                upk2(O2, o.x, o.y); upk2(O3, o.z, o.w);
                __stcs(((float4*)orow) + tid + NT, o);
            }
        }

        chain += GRIDN;
        if (chain >= NCHAIN) break;
        cpar ^= 1;
        xbase = x   + ((long)(chain >> 5) * CTOT + (chain & 31)) * LLEN;
        obase = out + ((long)(chain >> 5) * CTOT + (chain & 31)) * LLEN;
        // Write next chain's weights into the other swt half; covered by the
        // chain's i=0 edge barrier. Readers of the old half are all before the
        // previous chain's stage-2 barrier -> no race (different half anyway).
        load_swt(chain, cpar);
        // Reset recurrence state for the new chain.
        Y0 = Y1 = Y2 = Y3 = 0ull;
    }
}

extern "C" void kernel_launch(void* const* d_in, const int* in_sizes, int n_in,
                              void* d_out, int out_size)
{
    const float* x      = (const float*)d_in[0];
    const float* conv_w = (const float*)d_in[1];
    const float* conv_b = (const float*)d_in[2];
    const float* ln_g   = (const float*)d_in[3];
    const float* ln_b   = (const float*)d_in[4];
    const float* pw_w   = (const float*)d_in[5];
    const float* pw_b   = (const float*)d_in[6];
    float* out = (float*)d_out;

    const int smem_bytes = (4 * LLEN + 96 + 96) * (int)sizeof(float); // 66304
    cudaFuncSetAttribute(hdconv_encoder_kernel,
                         cudaFuncAttributeMaxDynamicSharedMemorySize, smem_bytes);

    dim3 grid(GRIDN); // persistent: 2 blocks per SM on 148 SMs
    dim3 block(NT);
    hdconv_encoder_kernel<<<grid, block, smem_bytes>>>(
        x, conv_w, conv_b, ln_g, ln_b, pw_w, pw_b, out);
}